// round 6
// baseline (speedup 1.0000x reference)
#include <cuda_runtime.h>
#include <math.h>

#define BB   2048
#define NN   200
#define DD   256
#define FT   128

// ---- scratch (device globals; no allocations allowed) ----
__device__ float g_G[2*256*256];    // Gcm[(h*256+e)*256 + d], scale 1/sqrt(128) folded
__device__ float g_C[2*256*256];    // Ccm[(h*256+e)*256 + d]
__device__ float g_W1t[384*128];    // W1t[e*128+f] = W1[f*384+e]
__device__ float g_W2t[128*128];
__device__ float g_KQ[BB*512];      // [b][h*256+d]
__device__ float g_CTX[BB*512];     // [b][h*256+e]

#define LOAD16(dst, ptr) do {                                              \
    const float4* _p = (const float4*)(ptr);                               \
    float4 _a=_p[0], _b=_p[1], _c=_p[2], _d=_p[3];                         \
    dst[0]=_a.x; dst[1]=_a.y; dst[2]=_a.z; dst[3]=_a.w;                    \
    dst[4]=_b.x; dst[5]=_b.y; dst[6]=_b.z; dst[7]=_b.w;                    \
    dst[8]=_c.x; dst[9]=_c.y; dst[10]=_c.z; dst[11]=_c.w;                  \
    dst[12]=_d.x; dst[13]=_d.y; dst[14]=_d.z; dst[15]=_d.w;                \
} while(0)

// ---------------- kernel 0: precompute G = Wk_h^T Wq_h (scaled), C = Wfc_h Wv_h
__global__ void k_prep(const float* __restrict__ Wq, const float* __restrict__ Wk,
                       const float* __restrict__ Wv, const float* __restrict__ Wfc){
    int h = blockIdx.x >> 8;
    int d = blockIdx.x & 255;
    int e = threadIdx.x;
    float g = 0.f, c = 0.f;
    #pragma unroll 4
    for (int j = 0; j < 128; j++){
        int hj = h*128 + j;
        float wk = Wk[hj*256 + d];      // broadcast
        float wq = Wq[hj*256 + e];      // coalesced
        float wf = Wfc[d*256 + hj];     // broadcast
        float wv = Wv[hj*256 + e];      // coalesced
        g += wk*wq;
        c += wf*wv;
    }
    g_G[(h*256+e)*256 + d] = g * 0.08838834764831845f;  // 1/sqrt(128)
    g_C[(h*256+e)*256 + d] = c;
}

__global__ void k_transpose(const float* __restrict__ W1, const float* __restrict__ W2){
    int i = blockIdx.x*blockDim.x + threadIdx.x;
    if (i < 384*128){ int e = i>>7, f = i&127; g_W1t[i] = W1[f*384+e]; }
    if (i < 128*128){ int e = i>>7, f = i&127; g_W2t[i] = W2[f*128+e]; }
}

// ---------------- kernel 1: KQ[b,h,:] = G_h @ q_in[b]   (TB=16 batches per CTA)
__global__ void k_kq(const float* __restrict__ src, const float* __restrict__ srct){
    __shared__ __align__(16) float sq[256*20];   // sq[e*20 + r], padded
    int b0 = blockIdx.x * 16;
    int tid = threadIdx.x;
    for (int i = tid; i < 16*256; i += 256){
        int r = i >> 8, dd = i & 255;
        float v = (dd < 128) ? src[(b0+r)*128 + dd] : srct[(b0+r)*128 + (dd-128)];
        sq[dd*20 + r] = v;
    }
    __syncthreads();
    int d = tid;
    for (int h = 0; h < 2; h++){
        float acc[16];
        #pragma unroll
        for (int r = 0; r < 16; r++) acc[r] = 0.f;
        const float* Gp = g_G + h*256*256 + d;
        for (int e = 0; e < 256; e++){
            float w = Gp[e*256];             // coalesced across d
            float vv[16]; LOAD16(vv, sq + e*20);
            #pragma unroll
            for (int r = 0; r < 16; r++) acc[r] += w * vv[r];
        }
        #pragma unroll
        for (int r = 0; r < 16; r++)
            g_KQ[((b0+r)*2 + h)*256 + d] = acc[r];
    }
}

// ---------------- kernel 2: streaming attention, one CTA per batch
// smem: kin[200*256] | kq[512] | lp[400] | red[4]
__global__ void k_attn(const float* __restrict__ seq, const float* __restrict__ seqt,
                       const unsigned char* __restrict__ mask, float* __restrict__ out){
    extern __shared__ __align__(16) float sm[];
    float* kin = sm;                  // 51200
    float* kq  = sm + 51200;          // 512
    float* lp  = sm + 51712;          // 400: logits, then probs (in place)
    float* red = sm + 52112;          // m0,s0,m1,s1
    int b = blockIdx.x;
    int tid = threadIdx.x;

    kq[tid]       = g_KQ[b*512 + tid];
    kq[tid + 256] = g_KQ[b*512 + 256 + tid];

    const float4* s4 = (const float4*)(seq  + (size_t)b*NN*128);
    const float4* t4 = (const float4*)(seqt + (size_t)b*NN*128);
    float4* kin4 = (float4*)kin;
    for (int i = tid; i < NN*64; i += 256){
        int row = i >> 6, p = i & 63;
        kin4[i] = (p < 32) ? s4[row*32 + p] : t4[row*32 + (p-32)];
    }
    __syncthreads();

    int warp = tid >> 5, lane = tid & 31;
    // logits: warp-per-n, both heads at once
    for (int n = warp; n < NN; n += 8){
        const float* kr = kin + n*256;
        bool mk = (lane == 0) ? (mask[(size_t)b*NN + n] != 0) : false;
        float s0 = 0.f, s1 = 0.f;
        #pragma unroll
        for (int k = 0; k < 8; k++){
            int dd = lane + 32*k;
            float v = kr[dd];
            s0 += v * kq[dd];
            s1 += v * kq[256 + dd];
        }
        #pragma unroll
        for (int off = 16; off > 0; off >>= 1){
            s0 += __shfl_down_sync(0xffffffffu, s0, off);
            s1 += __shfl_down_sync(0xffffffffu, s1, off);
        }
        if (lane == 0){
            lp[n]      = mk ? -1e10f : s0;
            lp[NN + n] = mk ? -1e10f : s1;
        }
    }
    __syncthreads();

    // softmax stats: warp 0 -> head 0, warp 1 -> head 1
    if (warp < 2){
        const float* L = lp + warp*NN;
        float m = -3.4e38f;
        for (int i = lane; i < NN; i += 32) m = fmaxf(m, L[i]);
        #pragma unroll
        for (int off = 16; off > 0; off >>= 1)
            m = fmaxf(m, __shfl_xor_sync(0xffffffffu, m, off));
        float s = 0.f;
        for (int i = lane; i < NN; i += 32) s += expf(L[i] - m);
        #pragma unroll
        for (int off = 16; off > 0; off >>= 1)
            s += __shfl_xor_sync(0xffffffffu, s, off);
        if (lane == 0){ red[warp*2] = m; red[warp*2 + 1] = s; }
    }
    __syncthreads();

    float m0 = red[0], is0 = 1.f/red[1], m1 = red[2], is1 = 1.f/red[3];
    for (int i = tid; i < 2*NN; i += 256){
        float m = (i < NN) ? m0 : m1;
        float is = (i < NN) ? is0 : is1;
        lp[i] = expf(lp[i] - m) * is;
    }
    __syncthreads();

    // attn_out = mean over heads
    for (int i = tid; i < NN; i += 256)
        out[(size_t)BB*128 + (size_t)b*NN + i] = 0.5f*(lp[i] + lp[NN + i]);

    // ctx[h][d] = sum_n p[h][n] * kin[n][d]
    float c0 = 0.f, c1 = 0.f;
    #pragma unroll 4
    for (int n = 0; n < NN; n++){
        float v = kin[n*256 + tid];
        c0 += lp[n]      * v;
        c1 += lp[NN + n] * v;
    }
    g_CTX[(size_t)b*512 + tid]       = c0;
    g_CTX[(size_t)b*512 + 256 + tid] = c1;
}

// ---------------- kernel 3: fused epilogue, TB=16 batches per CTA
// y = C@ctx + bfc + q_in ; LN ; merged=[h,src] ; h1=relu(W1@merged+b1) ; out=W2@h1+b2
__global__ void k_epi(const float* __restrict__ src,  const float* __restrict__ srct,
                      const float* __restrict__ bfc,  const float* __restrict__ lng,
                      const float* __restrict__ lnb,  const float* __restrict__ b1,
                      const float* __restrict__ b2,   float* __restrict__ out){
    extern __shared__ __align__(16) float sm[];
    float* ctxT = sm;            // 512*20
    float* merT = sm + 10240;    // 384*20
    float* h1T  = sm + 17920;    // 128*20
    float* smu  = sm + 20480;    // 16
    float* srs  = sm + 20496;    // 16
    int b0 = blockIdx.x * 16;
    int tid = threadIdx.x;

    for (int i = tid; i < 16*512; i += 256){
        int r = i >> 9, e = i & 511;
        ctxT[e*20 + r] = g_CTX[(size_t)(b0+r)*512 + e];
    }
    __syncthreads();

    int d = tid;
    float acc[16];
    {
        float bv = bfc[d];
        #pragma unroll
        for (int r = 0; r < 16; r++) acc[r] = bv;
    }
    const float* Cp = g_C + d;
    for (int e = 0; e < 512; e++){
        float w = Cp[e*256];                 // coalesced across d
        float vv[16]; LOAD16(vv, ctxT + e*20);
        #pragma unroll
        for (int r = 0; r < 16; r++) acc[r] += w * vv[r];
    }
    // + q_in, stash raw x
    #pragma unroll
    for (int r = 0; r < 16; r++){
        float q = (d < 128) ? src[(b0+r)*128 + d] : srct[(b0+r)*128 + d - 128];
        acc[r] += q;
        merT[d*20 + r] = acc[r];
    }
    __syncthreads();

    // LN stats (8 warps cover 16 rows)
    int warp = tid >> 5, lane = tid & 31;
    for (int rr = warp; rr < 16; rr += 8){
        float s = 0.f, sq = 0.f;
        #pragma unroll
        for (int k = 0; k < 8; k++){
            float v = merT[(lane + 32*k)*20 + rr];
            s += v; sq += v*v;
        }
        #pragma unroll
        for (int off = 16; off > 0; off >>= 1){
            s  += __shfl_xor_sync(0xffffffffu, s,  off);
            sq += __shfl_xor_sync(0xffffffffu, sq, off);
        }
        if (lane == 0){
            float mu  = s * (1.f/256.f);
            float var = sq * (1.f/256.f) - mu*mu;
            smu[rr] = mu;
            srs[rr] = rsqrtf(var + 1e-5f);
        }
    }
    __syncthreads();
    {
        float g = lng[d], bb = lnb[d];
        #pragma unroll
        for (int r = 0; r < 16; r++)
            merT[d*20 + r] = (acc[r] - smu[r]) * srs[r] * g + bb;
    }
    // append src to merged (cols 256..383)
    for (int i = tid; i < 16*128; i += 256){
        int r = i >> 7, f = i & 127;
        merT[(256 + f)*20 + r] = src[(b0+r)*128 + f];
    }
    __syncthreads();

    // stage B: h1 = relu(W1 @ merged + b1); threads: f = tid&127, half picks 8 rows
    int f = tid & 127, half = tid >> 7;
    {
        float a8[8];
        float bv = b1[f];
        #pragma unroll
        for (int r = 0; r < 8; r++) a8[r] = bv;
        for (int e = 0; e < 384; e++){
            float w = g_W1t[e*128 + f];
            const float4* p4 = (const float4*)(merT + e*20 + half*8);
            float4 va = p4[0], vb = p4[1];
            a8[0] += w*va.x; a8[1] += w*va.y; a8[2] += w*va.z; a8[3] += w*va.w;
            a8[4] += w*vb.x; a8[5] += w*vb.y; a8[6] += w*vb.z; a8[7] += w*vb.w;
        }
        #pragma unroll
        for (int r = 0; r < 8; r++)
            h1T[f*20 + half*8 + r] = fmaxf(a8[r], 0.f);
    }
    __syncthreads();

    // stage C: out_final = W2 @ h1 + b2
    {
        float a8[8];
        float bv = b2[f];
        #pragma unroll
        for (int r = 0; r < 8; r++) a8[r] = bv;
        for (int e = 0; e < 128; e++){
            float w = g_W2t[e*128 + f];
            const float4* p4 = (const float4*)(h1T + e*20 + half*8);
            float4 va = p4[0], vb = p4[1];
            a8[0] += w*va.x; a8[1] += w*va.y; a8[2] += w*va.z; a8[3] += w*va.w;
            a8[4] += w*vb.x; a8[5] += w*vb.y; a8[6] += w*vb.z; a8[7] += w*vb.w;
        }
        #pragma unroll
        for (int r = 0; r < 8; r++)
            out[(size_t)(b0 + half*8 + r)*128 + f] = a8[r];
    }
}

// ---------------- launch ----------------
extern "C" void kernel_launch(void* const* d_in, const int* in_sizes, int n_in,
                              void* d_out, int out_size){
    const float* src  = (const float*)d_in[0];
    const float* srct = (const float*)d_in[1];
    const float* seq  = (const float*)d_in[2];
    const float* seqt = (const float*)d_in[3];
    const float* Wq   = (const float*)d_in[4];
    const float* Wk   = (const float*)d_in[5];
    const float* Wv   = (const float*)d_in[6];
    const float* Wfc  = (const float*)d_in[7];
    const float* bfc  = (const float*)d_in[8];
    const float* lng  = (const float*)d_in[9];
    const float* lnb  = (const float*)d_in[10];
    const float* W1   = (const float*)d_in[11];
    const float* b1   = (const float*)d_in[12];
    const float* W2   = (const float*)d_in[13];
    const float* b2   = (const float*)d_in[14];
    const unsigned char* mask = (const unsigned char*)d_in[15];
    float* out = (float*)d_out;

    const int SMEM_ATTN = 52116 * 4;   // 208464 B
    const int SMEM_EPI  = 20512 * 4;   // 82048 B
    cudaFuncSetAttribute(k_attn, cudaFuncAttributeMaxDynamicSharedMemorySize, SMEM_ATTN);
    cudaFuncSetAttribute(k_epi,  cudaFuncAttributeMaxDynamicSharedMemorySize, SMEM_EPI);

    k_prep<<<512, 256>>>(Wq, Wk, Wv, Wfc);
    k_transpose<<<192, 256>>>(W1, W2);
    k_kq<<<BB/16, 256>>>(src, srct);
    k_attn<<<BB, 256, SMEM_ATTN>>>(seq, seqt, mask, out);
    k_epi<<<BB/16, 256, SMEM_EPI>>>(src, srct, bfc, lng, lnb, b1, b2, out);
}

// round 9
// speedup vs baseline: 1.5543x; 1.5543x over previous
#include <cuda_runtime.h>
#include <math.h>

#define BB    2048
#define NN    200
#define NPART 4
#define ROWS  50      // NN / NPART

// ---- scratch (device globals; no allocations allowed) ----
__device__ float g_G[2*256*256];       // Gcm[(h*256+e)*256 + d], scale folded
__device__ float g_C[2*256*256];       // Ccm[(h*256+e)*256 + d]
__device__ float g_W1t[384*128];
__device__ float g_W2t[128*128];
__device__ float g_KQ[BB*512];         // [b][h*256+d]
__device__ float g_CTX[BB*512];        // [b][h*256+e]  (combined)
__device__ float g_LOG[BB*2*NN];       // raw logits [b][h][n]
__device__ float g_PMS[BB*NPART*4];    // [bid][m0,s0,m1,s1]
__device__ float g_PCTX[BB*NPART*512]; // partial ctx

#define LOAD8(dst, ptr) do {                                               \
    const float4* _p = (const float4*)(ptr);                               \
    float4 _a=_p[0], _b=_p[1];                                             \
    dst[0]=_a.x; dst[1]=_a.y; dst[2]=_a.z; dst[3]=_a.w;                    \
    dst[4]=_b.x; dst[5]=_b.y; dst[6]=_b.z; dst[7]=_b.w;                    \
} while(0)

// ---------------- kernel 0: G = Wk_h^T Wq_h (scaled), C = Wfc_h Wv_h
__global__ void k_prep(const float* __restrict__ Wq, const float* __restrict__ Wk,
                       const float* __restrict__ Wv, const float* __restrict__ Wfc){
    int h = blockIdx.x >> 8;
    int d = blockIdx.x & 255;
    int e = threadIdx.x;
    float g = 0.f, c = 0.f;
    #pragma unroll 4
    for (int j = 0; j < 128; j++){
        int hj = h*128 + j;
        float wk = Wk[hj*256 + d];
        float wq = Wq[hj*256 + e];
        float wf = Wfc[d*256 + hj];
        float wv = Wv[hj*256 + e];
        g += wk*wq;
        c += wf*wv;
    }
    g_G[(h*256+e)*256 + d] = g * 0.08838834764831845f;
    g_C[(h*256+e)*256 + d] = c;
}

__global__ void k_transpose(const float* __restrict__ W1, const float* __restrict__ W2){
    int i = blockIdx.x*blockDim.x + threadIdx.x;
    if (i < 384*128){ int e = i>>7, f = i&127; g_W1t[i] = W1[f*384+e]; }
    if (i < 128*128){ int e = i>>7, f = i&127; g_W2t[i] = W2[f*128+e]; }
}

// ---------------- kernel 1: KQ = G_h @ q_in  (TB=8 batches per CTA, grid 256)
__global__ void k_kq(const float* __restrict__ src, const float* __restrict__ srct){
    __shared__ __align__(16) float sq[256*12];   // sq[e*12 + r]
    int b0 = blockIdx.x * 8;
    int tid = threadIdx.x;
    for (int i = tid; i < 8*256; i += 256){
        int r = i >> 8, dd = i & 255;
        float v = (dd < 128) ? src[(b0+r)*128 + dd] : srct[(b0+r)*128 + (dd-128)];
        sq[dd*12 + r] = v;
    }
    __syncthreads();
    int d = tid;
    for (int h = 0; h < 2; h++){
        float acc[8];
        #pragma unroll
        for (int r = 0; r < 8; r++) acc[r] = 0.f;
        const float* Gp = g_G + h*256*256 + d;
        for (int e = 0; e < 256; e++){
            float w = Gp[e*256];
            float vv[8]; LOAD8(vv, sq + e*12);
            #pragma unroll
            for (int r = 0; r < 8; r++) acc[r] += w * vv[r];
        }
        #pragma unroll
        for (int r = 0; r < 8; r++)
            g_KQ[((b0+r)*2 + h)*256 + d] = acc[r];
    }
}

// ---------------- kernel 2a: partial attention — 4 CTAs per batch, 50 rows each
// smem: kin[50*256] | kq[512] | lp[128] | red[4]   = 53776 B -> 4 CTAs/SM
__global__ void __launch_bounds__(256)
k_attn_part(const float* __restrict__ seq, const float* __restrict__ seqt,
            const unsigned char* __restrict__ mask){
    extern __shared__ __align__(16) float sm[];
    float* kin = sm;                  // 12800
    float* kq  = sm + 12800;          // 512
    float* lp  = sm + 13312;          // 128 (2*50 used)
    float* red = sm + 13440;          // 4
    int bid = blockIdx.x;
    int b   = bid >> 2;
    int n0  = (bid & 3) * ROWS;
    int tid = threadIdx.x;

    kq[tid]       = g_KQ[b*512 + tid];
    kq[tid + 256] = g_KQ[b*512 + 256 + tid];

    const float4* s4 = (const float4*)(seq  + (size_t)b*NN*128 + (size_t)n0*128);
    const float4* t4 = (const float4*)(seqt + (size_t)b*NN*128 + (size_t)n0*128);
    float4* kin4 = (float4*)kin;
    for (int i = tid; i < ROWS*64; i += 256){
        int row = i >> 6, p = i & 63;
        kin4[i] = (p < 32) ? s4[row*32 + p] : t4[row*32 + (p-32)];
    }
    __syncthreads();

    int warp = tid >> 5, lane = tid & 31;
    // logits for local rows, both heads
    for (int nl = warp; nl < ROWS; nl += 8){
        const float* kr = kin + nl*256;
        bool mk = (lane == 0) ? (mask[(size_t)b*NN + n0 + nl] != 0) : false;
        float s0 = 0.f, s1 = 0.f;
        #pragma unroll
        for (int k = 0; k < 8; k++){
            int dd = lane + 32*k;
            float v = kr[dd];
            s0 += v * kq[dd];
            s1 += v * kq[256 + dd];
        }
        #pragma unroll
        for (int off = 16; off > 0; off >>= 1){
            s0 += __shfl_down_sync(0xffffffffu, s0, off);
            s1 += __shfl_down_sync(0xffffffffu, s1, off);
        }
        if (lane == 0){
            float l0 = mk ? -1e10f : s0;
            float l1 = mk ? -1e10f : s1;
            lp[nl]        = l0;
            lp[ROWS + nl] = l1;
            g_LOG[(size_t)b*400 + n0 + nl]       = l0;
            g_LOG[(size_t)b*400 + 200 + n0 + nl] = l1;
        }
    }
    __syncthreads();

    // partial softmax stats: warp 0 -> head 0, warp 1 -> head 1
    if (warp < 2){
        const float* L = lp + warp*ROWS;
        float m = -3.4e38f;
        for (int i = lane; i < ROWS; i += 32) m = fmaxf(m, L[i]);
        #pragma unroll
        for (int off = 16; off > 0; off >>= 1)
            m = fmaxf(m, __shfl_xor_sync(0xffffffffu, m, off));
        float s = 0.f;
        for (int i = lane; i < ROWS; i += 32) s += expf(L[i] - m);
        #pragma unroll
        for (int off = 16; off > 0; off >>= 1)
            s += __shfl_xor_sync(0xffffffffu, s, off);
        if (lane == 0){ red[warp*2] = m; red[warp*2 + 1] = s; }
    }
    __syncthreads();

    float m0 = red[0], m1 = red[2];
    if (tid < 2*ROWS)
        lp[tid] = expf(lp[tid] - ((tid < ROWS) ? m0 : m1));
    __syncthreads();

    // partial ctx (unnormalized, relative to this part's max)
    float c0 = 0.f, c1 = 0.f;
    #pragma unroll 5
    for (int n = 0; n < ROWS; n++){
        float v = kin[n*256 + tid];
        c0 += lp[n]        * v;
        c1 += lp[ROWS + n] * v;
    }
    g_PCTX[(size_t)bid*512 + tid]       = c0;
    g_PCTX[(size_t)bid*512 + 256 + tid] = c1;
    if (tid < 4) g_PMS[bid*4 + tid] = red[tid];
}

// ---------------- kernel 2b: combine partials -> g_CTX + attn_out
__global__ void k_comb(float* __restrict__ out){
    __shared__ float w[NPART*2];     // per-part weight exp(m_p - m)/s per head
    __shared__ float smh[2], sish[2];
    int b = blockIdx.x;
    int tid = threadIdx.x;

    if (tid < 2){
        int h = tid;
        float m = -3.4e38f;
        #pragma unroll
        for (int p = 0; p < NPART; p++)
            m = fmaxf(m, g_PMS[(b*NPART + p)*4 + h*2]);
        float s = 0.f;
        #pragma unroll
        for (int p = 0; p < NPART; p++){
            float mp = g_PMS[(b*NPART + p)*4 + h*2];
            float sp = g_PMS[(b*NPART + p)*4 + h*2 + 1];
            s += sp * expf(mp - m);
        }
        float is = 1.f/s;
        smh[h] = m; sish[h] = is;
        #pragma unroll
        for (int p = 0; p < NPART; p++){
            float mp = g_PMS[(b*NPART + p)*4 + h*2];
            w[p*2 + h] = expf(mp - m) * is;
        }
    }
    __syncthreads();

    // combined ctx
    float c0 = 0.f, c1 = 0.f;
    #pragma unroll
    for (int p = 0; p < NPART; p++){
        c0 += g_PCTX[(size_t)(b*NPART + p)*512 + tid]       * w[p*2];
        c1 += g_PCTX[(size_t)(b*NPART + p)*512 + 256 + tid] * w[p*2 + 1];
    }
    g_CTX[(size_t)b*512 + tid]       = c0;
    g_CTX[(size_t)b*512 + 256 + tid] = c1;

    // attn_out = mean over heads of final probs
    float mm0 = smh[0], ii0 = sish[0], mm1 = smh[1], ii1 = sish[1];
    for (int n = tid; n < NN; n += 256){
        float p0 = expf(g_LOG[(size_t)b*400 + n]       - mm0) * ii0;
        float p1 = expf(g_LOG[(size_t)b*400 + 200 + n] - mm1) * ii1;
        out[(size_t)BB*128 + (size_t)b*NN + n] = 0.5f*(p0 + p1);
    }
}

// ---------------- kernel 3: fused epilogue, TB=8 batches per CTA (grid 256)
__global__ void k_epi(const float* __restrict__ src,  const float* __restrict__ srct,
                      const float* __restrict__ bfc,  const float* __restrict__ lng,
                      const float* __restrict__ lnb,  const float* __restrict__ b1,
                      const float* __restrict__ b2,   float* __restrict__ out){
    extern __shared__ __align__(16) float sm[];
    float* ctxT = sm;            // 512*12
    float* merT = sm + 6144;     // 384*12
    float* h1T  = sm + 10752;    // 128*12
    float* smu  = sm + 12288;    // 8
    float* srs  = sm + 12296;    // 8
    int b0 = blockIdx.x * 8;
    int tid = threadIdx.x;

    for (int i = tid; i < 8*512; i += 256){
        int r = i >> 9, e = i & 511;
        ctxT[e*12 + r] = g_CTX[(size_t)(b0+r)*512 + e];
    }
    __syncthreads();

    int d = tid;
    float acc[8];
    {
        float bv = bfc[d];
        #pragma unroll
        for (int r = 0; r < 8; r++) acc[r] = bv;
    }
    const float* Cp = g_C + d;
    for (int e = 0; e < 512; e++){
        float w = Cp[e*256];
        float vv[8]; LOAD8(vv, ctxT + e*12);
        #pragma unroll
        for (int r = 0; r < 8; r++) acc[r] += w * vv[r];
    }
    #pragma unroll
    for (int r = 0; r < 8; r++){
        float q = (d < 128) ? src[(b0+r)*128 + d] : srct[(b0+r)*128 + d - 128];
        acc[r] += q;
        merT[d*12 + r] = acc[r];
    }
    __syncthreads();

    // LN stats: 8 warps, one row each
    int warp = tid >> 5, lane = tid & 31;
    {
        int rr = warp;
        float s = 0.f, sq = 0.f;
        #pragma unroll
        for (int k = 0; k < 8; k++){
            float v = merT[(lane + 32*k)*12 + rr];
            s += v; sq += v*v;
        }
        #pragma unroll
        for (int off = 16; off > 0; off >>= 1){
            s  += __shfl_xor_sync(0xffffffffu, s,  off);
            sq += __shfl_xor_sync(0xffffffffu, sq, off);
        }
        if (lane == 0){
            float mu  = s * (1.f/256.f);
            float var = sq * (1.f/256.f) - mu*mu;
            smu[rr] = mu;
            srs[rr] = rsqrtf(var + 1e-5f);
        }
    }
    __syncthreads();
    {
        float g = lng[d], bb = lnb[d];
        #pragma unroll
        for (int r = 0; r < 8; r++)
            merT[d*12 + r] = (acc[r] - smu[r]) * srs[r] * g + bb;
    }
    for (int i = tid; i < 8*128; i += 256){
        int r = i >> 7, f = i & 127;
        merT[(256 + f)*12 + r] = src[(b0+r)*128 + f];
    }
    __syncthreads();

    // stage B: h1 = relu(W1 @ merged + b1); f = tid&127, half picks 4 rows
    int f = tid & 127, half = tid >> 7;
    {
        float a4[4];
        float bv = b1[f];
        #pragma unroll
        for (int r = 0; r < 4; r++) a4[r] = bv;
        for (int e = 0; e < 384; e++){
            float w = g_W1t[e*128 + f];
            float4 va = *(const float4*)(merT + e*12 + half*4);
            a4[0] += w*va.x; a4[1] += w*va.y; a4[2] += w*va.z; a4[3] += w*va.w;
        }
        #pragma unroll
        for (int r = 0; r < 4; r++)
            h1T[f*12 + half*4 + r] = fmaxf(a4[r], 0.f);
    }
    __syncthreads();

    // stage C: out_final = W2 @ h1 + b2
    {
        float a4[4];
        float bv = b2[f];
        #pragma unroll
        for (int r = 0; r < 4; r++) a4[r] = bv;
        for (int e = 0; e < 128; e++){
            float w = g_W2t[e*128 + f];
            float4 va = *(const float4*)(h1T + e*12 + half*4);
            a4[0] += w*va.x; a4[1] += w*va.y; a4[2] += w*va.z; a4[3] += w*va.w;
        }
        #pragma unroll
        for (int r = 0; r < 4; r++)
            out[(size_t)(b0 + half*4 + r)*128 + f] = a4[r];
    }
}

// ---------------- launch ----------------
extern "C" void kernel_launch(void* const* d_in, const int* in_sizes, int n_in,
                              void* d_out, int out_size){
    const float* src  = (const float*)d_in[0];
    const float* srct = (const float*)d_in[1];
    const float* seq  = (const float*)d_in[2];
    const float* seqt = (const float*)d_in[3];
    const float* Wq   = (const float*)d_in[4];
    const float* Wk   = (const float*)d_in[5];
    const float* Wv   = (const float*)d_in[6];
    const float* Wfc  = (const float*)d_in[7];
    const float* bfc  = (const float*)d_in[8];
    const float* lng  = (const float*)d_in[9];
    const float* lnb  = (const float*)d_in[10];
    const float* W1   = (const float*)d_in[11];
    const float* b1   = (const float*)d_in[12];
    const float* W2   = (const float*)d_in[13];
    const float* b2   = (const float*)d_in[14];
    const unsigned char* mask = (const unsigned char*)d_in[15];
    float* out = (float*)d_out;

    const int SMEM_ATTN = 13444 * 4;   // 53776 B -> 4 CTAs/SM
    const int SMEM_EPI  = 12304 * 4;   // 49216 B
    cudaFuncSetAttribute(k_attn_part, cudaFuncAttributeMaxDynamicSharedMemorySize, SMEM_ATTN);
    cudaFuncSetAttribute(k_epi,       cudaFuncAttributeMaxDynamicSharedMemorySize, SMEM_EPI);

    k_prep<<<512, 256>>>(Wq, Wk, Wv, Wfc);
    k_transpose<<<192, 256>>>(W1, W2);
    k_kq<<<BB/8, 256>>>(src, srct);
    k_attn_part<<<BB*NPART, 256, SMEM_ATTN>>>(seq, seqt, mask);
    k_comb<<<BB, 256>>>(out);
    k_epi<<<BB/8, 256, SMEM_EPI>>>(src, srct, bfc, lng, lnb, b1, b2, out);
}